// round 1
// baseline (speedup 1.0000x reference)
#include <cuda_runtime.h>
#include <cuda_bf16.h>

// Chamfer loss (nearest-target-vertex): B=4, N=16384, M=4096, D=3.
// d2[b,n] = min_m ||p - v||^2 = p2 + 2 * min_m (0.5*v2 - p.v)
// loss[b] = sum_n d2[b,n] / N

#define B_ 4
#define N_ 16384
#define M_ 4096
#define THREADS 256
#define PPT 2                       // points per thread
#define PTS_PER_BLOCK (THREADS * PPT)          // 512
#define BLOCKS_PER_BATCH (N_ / PTS_PER_BLOCK)  // 32
#define GRID (B_ * BLOCKS_PER_BATCH)           // 128
#define SMEM_BYTES (M_ * 16)                   // 64 KB: float4 per target

__global__ void chamfer_zero_kernel(float* out) {
    if (threadIdx.x < B_) out[threadIdx.x] = 0.0f;
}

__global__ __launch_bounds__(THREADS)
void chamfer_kernel(const float* __restrict__ src,
                    const float* __restrict__ tgt,
                    float* __restrict__ out) {
    extern __shared__ float4 sv[];   // (vx, vy, vz, 0.5*|v|^2)

    const int b     = blockIdx.x / BLOCKS_PER_BATCH;
    const int chunk = blockIdx.x % BLOCKS_PER_BATCH;

    // Cooperative load of this batch's target table into smem.
    const float* tb = tgt + (size_t)b * M_ * 3;
    for (int i = threadIdx.x; i < M_; i += THREADS) {
        float x = tb[3 * i + 0];
        float y = tb[3 * i + 1];
        float z = tb[3 * i + 2];
        sv[i] = make_float4(x, y, z, 0.5f * (x * x + y * y + z * z));
    }
    __syncthreads();

    // Each thread owns PPT source points (strided by THREADS for coalescing).
    float npx[PPT], npy[PPT], npz[PPT], p2[PPT], mn[PPT];
#pragma unroll
    for (int p = 0; p < PPT; p++) {
        int idx = b * N_ + chunk * PTS_PER_BLOCK + p * THREADS + threadIdx.x;
        float x = src[3 * idx + 0];
        float y = src[3 * idx + 1];
        float z = src[3 * idx + 2];
        npx[p] = -x; npy[p] = -y; npz[p] = -z;   // negate once: dot is pure FFMA
        p2[p]  = x * x + y * y + z * z;
        mn[p]  = 3.4e38f;
    }

    // Main loop: 1 LDS.128 broadcast + (3 FFMA + 1 FMNMX) per point per target.
#pragma unroll 8
    for (int m = 0; m < M_; m++) {
        float4 v = sv[m];
#pragma unroll
        for (int p = 0; p < PPT; p++) {
            float acc = fmaf(v.x, npx[p], v.w);
            acc = fmaf(v.y, npy[p], acc);
            acc = fmaf(v.z, npz[p], acc);
            mn[p] = fminf(mn[p], acc);
        }
    }

    // Per-thread partial sum of clamped d2.
    float local = 0.0f;
#pragma unroll
    for (int p = 0; p < PPT; p++)
        local += fmaxf(fmaf(2.0f, mn[p], p2[p]), 0.0f);

    // Warp reduce.
#pragma unroll
    for (int off = 16; off > 0; off >>= 1)
        local += __shfl_down_sync(0xffffffffu, local, off);

    __shared__ float warp_sums[THREADS / 32];
    if ((threadIdx.x & 31) == 0) warp_sums[threadIdx.x >> 5] = local;
    __syncthreads();

    if (threadIdx.x < THREADS / 32) {
        float s = warp_sums[threadIdx.x];
#pragma unroll
        for (int off = THREADS / 64; off > 0; off >>= 1)
            s += __shfl_down_sync(0xffu, s, off);
        if (threadIdx.x == 0)
            atomicAdd(&out[b], s * (1.0f / N_));
    }
}

extern "C" void kernel_launch(void* const* d_in, const int* in_sizes, int n_in,
                              void* d_out, int out_size) {
    const float* src = (const float*)d_in[0];
    const float* tgt = (const float*)d_in[1];
    // Defensive: identify src vs tgt by element count (src is 4x larger).
    if (n_in >= 2 && in_sizes[0] == B_ * M_ * 3 && in_sizes[1] == B_ * N_ * 3) {
        const float* t = src; src = tgt; tgt = t;
    }
    float* out = (float*)d_out;

    // Opt into 64 KB dynamic smem (idempotent; not a stream op, capture-safe).
    cudaFuncSetAttribute(chamfer_kernel,
                         cudaFuncAttributeMaxDynamicSharedMemorySize, SMEM_BYTES);

    chamfer_zero_kernel<<<1, 32>>>(out);
    chamfer_kernel<<<GRID, THREADS, SMEM_BYTES>>>(src, tgt, out);
}

// round 3
// speedup vs baseline: 1.1539x; 1.1539x over previous
#include <cuda_runtime.h>
#include <cuda_bf16.h>

// Chamfer loss (nearest-target-vertex): B=4, N=16384, M=4096, D=3.
// d2[b,n] = p2 + 2 * min_m (0.5*|v|^2 - p.v);  loss[b] = sum_n d2[b,n] / N
// Dot products via Blackwell packed fma.rn.f32x2 (2 targets/instr),
// mins as scalar FMNMX (alu pipe) on the aliased register halves.

#define B_ 4
#define N_ 16384
#define M_ 4096
#define MPAIRS (M_ / 2)
#define THREADS 256
#define PPT 2
#define PTS_PER_BLOCK (THREADS * PPT)          // 512
#define BLOCKS_PER_BATCH (N_ / PTS_PER_BLOCK)  // 32
#define GRID (B_ * BLOCKS_PER_BATCH)           // 128
#define SMEM_BYTES (M_ * 16)                   // 64 KB

typedef unsigned long long u64;

__device__ __forceinline__ u64 pack2(float lo, float hi) {
    u64 r;
    asm("mov.b64 %0, {%1, %2};" : "=l"(r) : "f"(lo), "f"(hi));
    return r;
}
__device__ __forceinline__ void unpack2(u64 v, float& lo, float& hi) {
    asm("mov.b64 {%0, %1}, %2;" : "=f"(lo), "=f"(hi) : "l"(v));
}
__device__ __forceinline__ u64 fma2(u64 a, u64 b, u64 c) {
    u64 d;
    asm("fma.rn.f32x2 %0, %1, %2, %3;" : "=l"(d) : "l"(a), "l"(b), "l"(c));
    return d;
}

__global__ void chamfer_zero_kernel(float* out) {
    if (threadIdx.x < B_) out[threadIdx.x] = 0.0f;
}

__global__ __launch_bounds__(THREADS)
void chamfer_kernel(const float* __restrict__ src,
                    const float* __restrict__ tgt,
                    float* __restrict__ out) {
    // Pair layout, 32 B per target pair j:
    //   [ vx_{2j}, vx_{2j+1}, vy_{2j}, vy_{2j+1} | vz_{2j}, vz_{2j+1}, w_{2j}, w_{2j+1} ]
    // where w = 0.5*|v|^2. One ulonglong2 LDS.128 yields two ready f32x2 operands.
    extern __shared__ float sv[];

    const int b     = blockIdx.x / BLOCKS_PER_BATCH;
    const int chunk = blockIdx.x % BLOCKS_PER_BATCH;

    const float* tb = tgt + (size_t)b * M_ * 3;
    for (int i = threadIdx.x; i < M_; i += THREADS) {
        float x = tb[3 * i + 0];
        float y = tb[3 * i + 1];
        float z = tb[3 * i + 2];
        float w = 0.5f * (x * x + y * y + z * z);
        int base = (i >> 1) * 8 + (i & 1);
        sv[base + 0] = x;
        sv[base + 2] = y;
        sv[base + 4] = z;
        sv[base + 6] = w;
    }
    __syncthreads();

    // Per-thread source points: negated coords packed as (v,v) f32x2 broadcasts.
    u64 npx2[PPT], npy2[PPT], npz2[PPT];
    float p2[PPT], mn0[PPT], mn1[PPT];
#pragma unroll
    for (int p = 0; p < PPT; p++) {
        int idx = b * N_ + chunk * PTS_PER_BLOCK + p * THREADS + threadIdx.x;
        float x = src[3 * idx + 0];
        float y = src[3 * idx + 1];
        float z = src[3 * idx + 2];
        npx2[p] = pack2(-x, -x);
        npy2[p] = pack2(-y, -y);
        npz2[p] = pack2(-z, -z);
        p2[p]   = x * x + y * y + z * z;
        mn0[p]  = 3.4e38f;
        mn1[p]  = 3.4e38f;
    }

    const ulonglong2* s2 = (const ulonglong2*)sv;
    // Per pair-iter per point: 3 FFMA2 (fma pipe) + 2 FMNMX (alu pipe).
#pragma unroll 8
    for (int j = 0; j < MPAIRS; j++) {
        ulonglong2 LA = s2[2 * j];       // (vx2, vy2)
        ulonglong2 LB = s2[2 * j + 1];   // (vz2, w2)
#pragma unroll
        for (int p = 0; p < PPT; p++) {
            u64 acc = fma2(LA.x, npx2[p], LB.y);
            acc = fma2(LA.y, npy2[p], acc);
            acc = fma2(LB.x, npz2[p], acc);
            float a0, a1;
            unpack2(acc, a0, a1);        // register aliasing: ~free
            mn0[p] = fminf(mn0[p], a0);  // two independent min chains
            mn1[p] = fminf(mn1[p], a1);
        }
    }

    // Epilogue: fold the two chains, clamp, per-thread sum.
    float local = 0.0f;
#pragma unroll
    for (int p = 0; p < PPT; p++) {
        float mn = fminf(mn0[p], mn1[p]);
        local += fmaxf(fmaf(2.0f, mn, p2[p]), 0.0f);
    }

#pragma unroll
    for (int off = 16; off > 0; off >>= 1)
        local += __shfl_down_sync(0xffffffffu, local, off);

    __shared__ float warp_sums[THREADS / 32];
    if ((threadIdx.x & 31) == 0) warp_sums[threadIdx.x >> 5] = local;
    __syncthreads();

    if (threadIdx.x < THREADS / 32) {
        float s = warp_sums[threadIdx.x];
#pragma unroll
        for (int off = THREADS / 64; off > 0; off >>= 1)
            s += __shfl_down_sync(0xffu, s, off);
        if (threadIdx.x == 0)
            atomicAdd(&out[b], s * (1.0f / N_));
    }
}

extern "C" void kernel_launch(void* const* d_in, const int* in_sizes, int n_in,
                              void* d_out, int out_size) {
    const float* src = (const float*)d_in[0];
    const float* tgt = (const float*)d_in[1];
    if (n_in >= 2 && in_sizes[0] == B_ * M_ * 3 && in_sizes[1] == B_ * N_ * 3) {
        const float* t = src; src = tgt; tgt = t;
    }
    float* out = (float*)d_out;

    cudaFuncSetAttribute(chamfer_kernel,
                         cudaFuncAttributeMaxDynamicSharedMemorySize, SMEM_BYTES);

    chamfer_zero_kernel<<<1, 32>>>(out);
    chamfer_kernel<<<GRID, THREADS, SMEM_BYTES>>>(src, tgt, out);
}

// round 4
// speedup vs baseline: 1.6485x; 1.4287x over previous
#include <cuda_runtime.h>
#include <cuda_bf16.h>

// Chamfer loss (nearest-target-vertex): B=4, N=16384, M=4096, D=3.
// d2[b,n] = p2 + 2 * min_m (0.5*|v|^2 - p.v);  loss[b] = sum_n d2[b,n] / N
//
// Two-pass, M-split x8 for occupancy:
//   pass 1: 1024 blocks, each 512 points x 512 targets -> per-point partial
//           min score into __device__ scratch (pure stores, no reduction).
//   pass 2: fold 8 partials, clamp, reduce to out.

#define B_ 4
#define N_ 16384
#define M_ 4096
#define SPLITS 8
#define M_PER (M_ / SPLITS)            // 512 targets per block
#define PAIRS_PER (M_PER / 2)          // 256 target pairs
#define THREADS 256
#define PPT 2
#define PTS_PER_BLOCK (THREADS * PPT)            // 512
#define CHUNKS (N_ / PTS_PER_BLOCK)              // 32
#define GRID1 (B_ * CHUNKS * SPLITS)             // 1024
#define SMEM_BYTES (M_PER * 16)                  // 8 KB

typedef unsigned long long u64;

__device__ float g_partial[SPLITS][B_ * N_];     // 2 MB scratch

__device__ __forceinline__ u64 pack2(float lo, float hi) {
    u64 r;
    asm("mov.b64 %0, {%1, %2};" : "=l"(r) : "f"(lo), "f"(hi));
    return r;
}
__device__ __forceinline__ void unpack2(u64 v, float& lo, float& hi) {
    asm("mov.b64 {%0, %1}, %2;" : "=f"(lo), "=f"(hi) : "l"(v));
}
__device__ __forceinline__ u64 fma2(u64 a, u64 b, u64 c) {
    u64 d;
    asm("fma.rn.f32x2 %0, %1, %2, %3;" : "=l"(d) : "l"(a), "l"(b), "l"(c));
    return d;
}

__global__ __launch_bounds__(THREADS)
void chamfer_pass1(const float* __restrict__ src,
                   const float* __restrict__ tgt,
                   float* __restrict__ out) {
    extern __shared__ float sv[];   // 256 pairs x 32B (f32x2-ready layout)

    if (blockIdx.x == 0 && threadIdx.x < B_) out[threadIdx.x] = 0.0f;

    const int s     = blockIdx.x % SPLITS;
    const int t     = blockIdx.x / SPLITS;
    const int b     = t / CHUNKS;
    const int chunk = t % CHUNKS;

    // Load this block's 512-target tile (w = 0.5*|v|^2).
    const float* tb = tgt + (size_t)b * M_ * 3 + (size_t)s * M_PER * 3;
    for (int i = threadIdx.x; i < M_PER; i += THREADS) {
        float x = tb[3 * i + 0];
        float y = tb[3 * i + 1];
        float z = tb[3 * i + 2];
        float w = 0.5f * (x * x + y * y + z * z);
        int base = (i >> 1) * 8 + (i & 1);
        sv[base + 0] = x;
        sv[base + 2] = y;
        sv[base + 4] = z;
        sv[base + 6] = w;
    }
    __syncthreads();

    // Per-thread source points, negated + broadcast into f32x2 regs.
    u64 npx2[PPT], npy2[PPT], npz2[PPT];
    float mn0[PPT], mn1[PPT];
    int pidx[PPT];
#pragma unroll
    for (int p = 0; p < PPT; p++) {
        pidx[p] = b * N_ + chunk * PTS_PER_BLOCK + p * THREADS + threadIdx.x;
        float x = src[3 * pidx[p] + 0];
        float y = src[3 * pidx[p] + 1];
        float z = src[3 * pidx[p] + 2];
        npx2[p] = pack2(-x, -x);
        npy2[p] = pack2(-y, -y);
        npz2[p] = pack2(-z, -z);
        mn0[p] = 3.4e38f;
        mn1[p] = 3.4e38f;
    }

    const ulonglong2* s2 = (const ulonglong2*)sv;
    // Per pair-iter per point: 3 FFMA2 (fma pipe) + 2 FMNMX (alu pipe).
#pragma unroll 8
    for (int j = 0; j < PAIRS_PER; j++) {
        ulonglong2 LA = s2[2 * j];       // (vx2, vy2)
        ulonglong2 LB = s2[2 * j + 1];   // (vz2, w2)
#pragma unroll
        for (int p = 0; p < PPT; p++) {
            u64 acc = fma2(LA.x, npx2[p], LB.y);
            acc = fma2(LA.y, npy2[p], acc);
            acc = fma2(LB.x, npz2[p], acc);
            float a0, a1;
            unpack2(acc, a0, a1);
            mn0[p] = fminf(mn0[p], a0);
            mn1[p] = fminf(mn1[p], a1);
        }
    }

    // Raw partial-min stores; all combining happens in pass 2.
#pragma unroll
    for (int p = 0; p < PPT; p++)
        g_partial[s][pidx[p]] = fminf(mn0[p], mn1[p]);
}

#define THREADS2 256
#define PPT2 4
#define PTS_PER_BLOCK2 (THREADS2 * PPT2)   // 1024
#define GRID2 (B_ * N_ / PTS_PER_BLOCK2)   // 64 (each block within one batch)

__global__ __launch_bounds__(THREADS2)
void chamfer_pass2(const float* __restrict__ src,
                   float* __restrict__ out) {
    const int base = blockIdx.x * PTS_PER_BLOCK2;
    const int b    = base >> 14;           // N_ = 16384 points per batch

    float local = 0.0f;
#pragma unroll
    for (int k = 0; k < PPT2; k++) {
        int i = base + k * THREADS2 + threadIdx.x;
        float mn = g_partial[0][i];
#pragma unroll
        for (int s = 1; s < SPLITS; s++)
            mn = fminf(mn, g_partial[s][i]);
        float x = src[3 * i + 0];
        float y = src[3 * i + 1];
        float z = src[3 * i + 2];
        float p2 = x * x + y * y + z * z;
        local += fmaxf(fmaf(2.0f, mn, p2), 0.0f);
    }

#pragma unroll
    for (int off = 16; off > 0; off >>= 1)
        local += __shfl_down_sync(0xffffffffu, local, off);

    __shared__ float warp_sums[THREADS2 / 32];
    if ((threadIdx.x & 31) == 0) warp_sums[threadIdx.x >> 5] = local;
    __syncthreads();

    if (threadIdx.x < THREADS2 / 32) {
        float v = warp_sums[threadIdx.x];
#pragma unroll
        for (int off = THREADS2 / 64; off > 0; off >>= 1)
            v += __shfl_down_sync(0xffu, v, off);
        if (threadIdx.x == 0)
            atomicAdd(&out[b], v * (1.0f / N_));
    }
}

extern "C" void kernel_launch(void* const* d_in, const int* in_sizes, int n_in,
                              void* d_out, int out_size) {
    const float* src = (const float*)d_in[0];
    const float* tgt = (const float*)d_in[1];
    if (n_in >= 2 && in_sizes[0] == B_ * M_ * 3 && in_sizes[1] == B_ * N_ * 3) {
        const float* t = src; src = tgt; tgt = t;
    }
    float* out = (float*)d_out;

    chamfer_pass1<<<GRID1, THREADS, SMEM_BYTES>>>(src, tgt, out);
    chamfer_pass2<<<GRID2, THREADS2>>>(src, out);
}